// round 15
// baseline (speedup 1.0000x reference)
#include <cuda_runtime.h>
#include <cuda_bf16.h>
#include <cstdint>

#define NB 2
#define NS 1024
#define FIN 768
#define NE 768
#define NH 12
#define NBH (NB * NH)
#define NDH 64
#define NFH 64
#define NSPLIT 16
#define OSPL (NS / NSPLIT)   // 64 tokens per split (pass2)
#define NSG 16               // g1 splits (64 tokens each, fused in nnmf)
#define MIN_POS 1e-6f
#define EPSV 1e-20f
#define K3 2304              // tripled K for bf16-split GEMM
#define HSTR 68              // feature-major row stride (floats): 64 tokens + 4 pad
#define NN_SMEM_BYTES ((4096 + 4096 + 64 * HSTR * 2) * 4)

typedef unsigned long long u64;

// ---------------- scratch (device globals; no allocation) ----------------
__device__ __align__(16) float g_Wn[NFH * NDH];                 // normalized W [f][d]
__device__ __align__(16) float g_Wt[NDH * NFH];                 // transposed normalized W [d][f]
__device__ __align__(16) float g_rec0[NDH];                     // (1/64)*colsum(W) — iteration-0 rec
__device__ __align__(16) __nv_bfloat16 g_Abf[2048 * K3];        // [hi | hi | lo] of X
__device__ __align__(16) __nv_bfloat16 g_Wbf[768 * K3];         // [hi | lo | hi] of embed_w
__device__ __align__(16) float g_xe[NB * NS * NE];              // clipped embed output
__device__ __align__(16) float g_h[NBH * NS * NFH];             // h   [bh][s][f]
__device__ __align__(16) float g_hri[NBH * NS * NDH];           // rec*inp [bh][s][d]
__device__ __align__(16) float g_G1p[NBH * NSG * 64 * 64];      // partial h^T*hri
__device__ __align__(16) float g_G1[NBH * 64 * 64];             // reduced h^T*hri
__device__ __align__(16) float g_Mp[NBH * NSPLIT * 64 * 64];    // partial h^T*(w01*hri)
__device__ __align__(16) float g_M[NBH * 64 * 64];              // reduced M
__device__ __align__(16) float g_csp[NBH * NSG * 64];           // partial colsum(h)
__device__ __align__(16) float g_c2p[NBH * NSPLIT * 64];        // partial c2
__device__ __align__(16) float g_aiA[NBH * 64];                 // arec_inv iter0
__device__ __align__(16) float g_aiB[NBH * 64];                 // arec_inv iter1
__device__ __align__(16) float g_cfin[NB * NE];                 // final mixed row per batch
__device__ __align__(16) float g_yrow[NB * FIN];                // final projected row per batch

// ---------------- helpers ----------------
__device__ __forceinline__ float red16(float v) {
    v += __shfl_xor_sync(0xffffffffu, v, 8);
    v += __shfl_xor_sync(0xffffffffu, v, 4);
    v += __shfl_xor_sync(0xffffffffu, v, 2);
    v += __shfl_xor_sync(0xffffffffu, v, 1);
    return v;
}
__device__ __forceinline__ float red32(float v) {
    v += __shfl_xor_sync(0xffffffffu, v, 16);
    return red16(v);
}
__device__ __forceinline__ uint32_t pack2(__nv_bfloat16 a, __nv_bfloat16 b) {
    __nv_bfloat162 t = __halves2bfloat162(a, b);
    return *reinterpret_cast<uint32_t*>(&t);
}
__device__ __forceinline__ void ldsm4(uint32_t* r, uint32_t addr) {
    asm volatile("ldmatrix.sync.aligned.m8n8.x4.shared.b16 {%0,%1,%2,%3}, [%4];"
                 : "=r"(r[0]), "=r"(r[1]), "=r"(r[2]), "=r"(r[3]) : "r"(addr));
}
__device__ __forceinline__ void mma_bf16(float* c, const uint32_t* a, uint32_t b0, uint32_t b1) {
    asm volatile(
        "mma.sync.aligned.m16n8k16.row.col.f32.bf16.bf16.f32 "
        "{%0,%1,%2,%3}, {%4,%5,%6,%7}, {%8,%9}, {%0,%1,%2,%3};\n"
        : "+f"(c[0]), "+f"(c[1]), "+f"(c[2]), "+f"(c[3])
        : "r"(a[0]), "r"(a[1]), "r"(a[2]), "r"(a[3]), "r"(b0), "r"(b1));
}
// packed fp32x2 helpers (FFMA2 is PTX-only; ptxas never auto-fuses)
__device__ __forceinline__ u64 fma2(u64 a, u64 b, u64 c) {
    u64 d;
    asm("fma.rn.f32x2 %0, %1, %2, %3;" : "=l"(d) : "l"(a), "l"(b), "l"(c));
    return d;
}
__device__ __forceinline__ u64 dup2(float x) {
    u64 d;
    uint32_t r = __float_as_uint(x);
    asm("mov.b64 %0, {%1, %2};" : "=l"(d) : "r"(r), "r"(r));
    return d;
}
__device__ __forceinline__ float2 unpk2(u64 v) {
    uint32_t lo, hi;
    asm("mov.b64 {%0, %1}, %2;" : "=r"(lo), "=r"(hi) : "l"(v));
    return make_float2(__uint_as_float(lo), __uint_as_float(hi));
}

// ---------------- K1: normalize nnmf_w rows (+ transpose + rec0) ----------------
__global__ void wnorm_kernel(const float* __restrict__ nnmf_w) {
    int f = threadIdx.x;  // 0..63
    float s = 0.f;
#pragma unroll
    for (int d = 0; d < NDH; ++d) s += nnmf_w[f * NDH + d];
    s = fmaxf(s, EPSV);
    float inv = 1.f / s;
#pragma unroll
    for (int d = 0; d < NDH; ++d) {
        float v = nnmf_w[f * NDH + d] * inv;
        g_Wn[f * NDH + d] = v;
        g_Wt[d * NFH + f] = v;
    }
    __syncthreads();
    {
        int d = f;
        float c = 0.f;
#pragma unroll
        for (int ff = 0; ff < NFH; ++ff) c += g_Wn[ff * NDH + d];
        g_rec0[d] = c * (1.f / 64.f);
    }
}

// ---------------- K2a: bf16 split conversion of X and embed_w ----------------
__global__ void __launch_bounds__(256) conv_kernel(const float* __restrict__ X,
                                                   const float* __restrict__ Wm) {
    int i = blockIdx.x * 256 + threadIdx.x;
    int row = i / 192, q = (i % 192) * 4;
    const float* src = (row < 2048) ? X + (size_t)row * 768 + q
                                    : Wm + (size_t)(row - 2048) * 768 + q;
    float4 v = *(const float4*)src;
    float xs[4] = {v.x, v.y, v.z, v.w};
    __nv_bfloat16 hi[4], lo[4];
#pragma unroll
    for (int j = 0; j < 4; ++j) {
        hi[j] = __float2bfloat16(xs[j]);
        lo[j] = __float2bfloat16(xs[j] - __bfloat162float(hi[j]));
    }
    uint2 hv = make_uint2(pack2(hi[0], hi[1]), pack2(hi[2], hi[3]));
    uint2 lv = make_uint2(pack2(lo[0], lo[1]), pack2(lo[2], lo[3]));
    if (row < 2048) {
        __nv_bfloat16* dst = g_Abf + (size_t)row * K3 + q;
        *(uint2*)(dst)        = hv;
        *(uint2*)(dst + 768)  = hv;
        *(uint2*)(dst + 1536) = lv;
    } else {
        __nv_bfloat16* dst = g_Wbf + (size_t)(row - 2048) * K3 + q;
        *(uint2*)(dst)        = hv;
        *(uint2*)(dst + 768)  = lv;
        *(uint2*)(dst + 1536) = hv;
    }
}

// ---------------- K2b: embed GEMM, bf16 mma, double-buffered ----------------
__global__ void __launch_bounds__(256) embed_mma_kernel(const float* __restrict__ bias) {
    __shared__ __align__(16) __nv_bfloat16 As[2][128 * 40];
    __shared__ __align__(16) __nv_bfloat16 Bs[2][64 * 40];
    int tid = threadIdx.x;
    int bm = blockIdx.y * 128, bn = blockIdx.x * 64;
    int wid = tid >> 5, lane = tid & 31;
    int wm = wid & 3, wn = wid >> 2;

    float c[2][4][4];
#pragma unroll
    for (int mt = 0; mt < 2; ++mt)
#pragma unroll
        for (int nt = 0; nt < 4; ++nt)
#pragma unroll
            for (int r = 0; r < 4; ++r) c[mt][nt][r] = 0.f;

    const uint32_t ABUF = 128 * 40 * 2;
    const uint32_t BBUF = 64 * 40 * 2;
    uint32_t a_base[2], b_base[2];
#pragma unroll
    for (int mt = 0; mt < 2; ++mt) {
        int row = wm * 32 + mt * 16 + (lane & 15);
        int colhalf = lane >> 4;
        a_base[mt] = (uint32_t)__cvta_generic_to_shared(&As[0][row * 40 + colhalf * 8]);
    }
#pragma unroll
    for (int bt = 0; bt < 2; ++bt) {
        int n = wn * 32 + bt * 16 + ((lane >> 4) << 3) + (lane & 7);
        int khalf = (lane >> 3) & 1;
        b_base[bt] = (uint32_t)__cvta_generic_to_shared(&Bs[0][n * 40 + khalf * 8]);
    }

    int am0 = tid >> 2, ac0 = (tid & 3) * 8;
    int am1 = (tid + 256) >> 2, ac1 = ((tid + 256) & 3) * 8;
    int bn0 = tid >> 2, bc0 = (tid & 3) * 8;
    const __nv_bfloat16* arow0 = g_Abf + (size_t)(bm + am0) * K3 + ac0;
    const __nv_bfloat16* arow1 = g_Abf + (size_t)(bm + am1) * K3 + ac1;
    const __nv_bfloat16* brow0 = g_Wbf + (size_t)(bn + bn0) * K3 + bc0;

    {
        *(uint4*)&As[0][am0 * 40 + ac0] = *(const uint4*)(arow0);
        *(uint4*)&As[0][am1 * 40 + ac1] = *(const uint4*)(arow1);
        *(uint4*)&Bs[0][bn0 * 40 + bc0] = *(const uint4*)(brow0);
    }
    __syncthreads();

    for (int ks = 0; ks < 72; ++ks) {
        int cur = ks & 1, nxt = cur ^ 1;
        uint4 na0, na1, nb;
        if (ks < 71) {
            int k0n = (ks + 1) * 32;
            na0 = *(const uint4*)(arow0 + k0n);
            na1 = *(const uint4*)(arow1 + k0n);
            nb  = *(const uint4*)(brow0 + k0n);
        }
        uint32_t aoff = cur * ABUF, boff = cur * BBUF;
#pragma unroll
        for (int kh = 0; kh < 2; ++kh) {
            int kk = kh * 16;
            uint32_t a[2][4], b[2][4];
            ldsm4(a[0], a_base[0] + aoff + kk * 2);
            ldsm4(a[1], a_base[1] + aoff + kk * 2);
            ldsm4(b[0], b_base[0] + boff + kk * 2);
            ldsm4(b[1], b_base[1] + boff + kk * 2);
#pragma unroll
            for (int mt = 0; mt < 2; ++mt)
#pragma unroll
                for (int nt = 0; nt < 4; ++nt)
                    mma_bf16(c[mt][nt], a[mt], b[nt >> 1][(nt & 1) * 2], b[nt >> 1][(nt & 1) * 2 + 1]);
        }
        if (ks < 71) {
            *(uint4*)&As[nxt][am0 * 40 + ac0] = na0;
            *(uint4*)&As[nxt][am1 * 40 + ac1] = na1;
            *(uint4*)&Bs[nxt][bn0 * 40 + bc0] = nb;
        }
        __syncthreads();
    }

#pragma unroll
    for (int mt = 0; mt < 2; ++mt) {
#pragma unroll
        for (int nt = 0; nt < 4; ++nt) {
            int m0 = bm + wm * 32 + mt * 16 + (lane >> 2);
            int n0 = bn + wn * 32 + nt * 8 + (lane & 3) * 2;
            float2 bv = *(const float2*)&bias[n0];
            float2 o0, o1;
            o0.x = fmaxf(c[mt][nt][0] + bv.x, MIN_POS);
            o0.y = fmaxf(c[mt][nt][1] + bv.y, MIN_POS);
            o1.x = fmaxf(c[mt][nt][2] + bv.x, MIN_POS);
            o1.y = fmaxf(c[mt][nt][3] + bv.y, MIN_POS);
            *(float2*)&g_xe[(size_t)m0 * NE + n0] = o0;
            *(float2*)&g_xe[(size_t)(m0 + 8) * NE + n0] = o1;
        }
    }
}

// ---------------- K3: fused NNMF — warp-private token columns, __syncwarp inner sync ----------------
// thread (g = tid>>4, d4 = tid&15); warp w owns token columns 8w..8w+7 of s_ht/s_rt
// (disjoint across warps), and red16 shuffles stay inside 16-lane groups, so the
// iteration loop needs only warp-level sync. Block barriers remain only around the
// cooperative W load and the cross-warp G1 tail.
__global__ void __launch_bounds__(256, 3) nnmf_kernel() {
    extern __shared__ float sm[];
    float* sW   = sm;
    float* sWt  = sm + 4096;
    float* s_ht = sm + 8192;
    float* s_rt = sm + 8192 + 64 * HSTR;

    int head = blockIdx.y;
    int tile = blockIdx.x;
    int tid = threadIdx.x;
    int d4 = tid & 15;
    int g = tid >> 4;
    int tokbase = tile * 64;

    for (int i = tid; i < 4096; i += 256) sW[i] = g_Wn[i];
    for (int i = tid; i < 4096; i += 256) sWt[i] = g_Wt[i];

    float inp[4][4];
#pragma unroll
    for (int t = 0; t < 4; ++t) {
        int tok = tokbase + g * 4 + t;
        float4 x = *(const float4*)&g_xe[(size_t)tok * NE + head * 64 + d4 * 4];
        float s = red16(x.x + x.y + x.z + x.w);
        float iv = 1.f / fmaxf(s, EPSV);
        inp[t][0] = x.x * iv; inp[t][1] = x.y * iv; inp[t][2] = x.z * iv; inp[t][3] = x.w * iv;
    }

    {
        float4 r0 = *(const float4*)&g_rec0[d4 * 4];
        float rd[4] = {1.f / fmaxf(r0.x, MIN_POS), 1.f / fmaxf(r0.y, MIN_POS),
                       1.f / fmaxf(r0.z, MIN_POS), 1.f / fmaxf(r0.w, MIN_POS)};
#pragma unroll
        for (int i = 0; i < 4; ++i)
            *(float4*)&s_rt[(d4 * 4 + i) * HSTR + g * 4] =
                make_float4(inp[0][i] * rd[i], inp[1][i] * rd[i],
                            inp[2][i] * rd[i], inp[3][i] * rd[i]);
    }
    __syncthreads();   // W smem load complete (also covers initial s_rt)

    const float hinit = 1.f / 64.f;
    float hr[4][4];
    float ri[4][4];

    for (int it = 0; it < 3; ++it) {
        if (it > 0) {
            u64 a[4][2] = {};
#pragma unroll 8
            for (int ff = 0; ff < 64; ++ff) {
                ulonglong2 hp = *(const ulonglong2*)&s_ht[ff * HSTR + g * 4];
                float4 w = *(const float4*)&sW[ff * 64 + d4 * 4];
                u64 w0 = dup2(w.x), w1 = dup2(w.y), w2 = dup2(w.z), w3 = dup2(w.w);
                a[0][0] = fma2(w0, hp.x, a[0][0]); a[0][1] = fma2(w0, hp.y, a[0][1]);
                a[1][0] = fma2(w1, hp.x, a[1][0]); a[1][1] = fma2(w1, hp.y, a[1][1]);
                a[2][0] = fma2(w2, hp.x, a[2][0]); a[2][1] = fma2(w2, hp.y, a[2][1]);
                a[3][0] = fma2(w3, hp.x, a[3][0]); a[3][1] = fma2(w3, hp.y, a[3][1]);
            }
            float av[4][4];
#pragma unroll
            for (int i = 0; i < 4; ++i) {
                float2 u0 = unpk2(a[i][0]), u1 = unpk2(a[i][1]);
                av[0][i] = fmaxf(u0.x, MIN_POS); av[1][i] = fmaxf(u0.y, MIN_POS);
                av[2][i] = fmaxf(u1.x, MIN_POS); av[3][i] = fmaxf(u1.y, MIN_POS);
            }
            if (it == 2) {
#pragma unroll
                for (int t = 0; t < 4; ++t)
#pragma unroll
                    for (int i = 0; i < 4; ++i) ri[t][i] = av[t][i] * inp[t][i];
            }
#pragma unroll
            for (int i = 0; i < 4; ++i) {
                float q0 = __fdividef(inp[0][i], av[0][i]);
                float q1 = __fdividef(inp[1][i], av[1][i]);
                float q2 = __fdividef(inp[2][i], av[2][i]);
                float q3 = __fdividef(inp[3][i], av[3][i]);
                *(float4*)&s_rt[(d4 * 4 + i) * HSTR + g * 4] = make_float4(q0, q1, q2, q3);
            }
            __syncwarp();   // s_rt columns are warp-private
        }

        u64 b[4][2] = {};
#pragma unroll 8
        for (int d = 0; d < 64; ++d) {
            ulonglong2 rp = *(const ulonglong2*)&s_rt[d * HSTR + g * 4];
            float4 wt = *(const float4*)&sWt[d * 64 + d4 * 4];
            u64 w0 = dup2(wt.x), w1 = dup2(wt.y), w2 = dup2(wt.z), w3 = dup2(wt.w);
            b[0][0] = fma2(w0, rp.x, b[0][0]); b[0][1] = fma2(w0, rp.y, b[0][1]);
            b[1][0] = fma2(w1, rp.x, b[1][0]); b[1][1] = fma2(w1, rp.y, b[1][1]);
            b[2][0] = fma2(w2, rp.x, b[2][0]); b[2][1] = fma2(w2, rp.y, b[2][1]);
            b[3][0] = fma2(w3, rp.x, b[3][0]); b[3][1] = fma2(w3, rp.y, b[3][1]);
        }
        float bv[4][4];
#pragma unroll
        for (int i = 0; i < 4; ++i) {
            float2 u0 = unpk2(b[i][0]), u1 = unpk2(b[i][1]);
            bv[0][i] = u0.x; bv[1][i] = u0.y; bv[2][i] = u1.x; bv[3][i] = u1.y;
        }
#pragma unroll
        for (int t = 0; t < 4; ++t) {
            float hn[4];
#pragma unroll
            for (int i = 0; i < 4; ++i) {
                float pre = (it == 0) ? hinit : hr[t][i];
                hn[i] = fmaxf(pre * bv[t][i], MIN_POS);
            }
            float hs = red16(hn[0] + hn[1] + hn[2] + hn[3]);
            float ih = 1.f / fmaxf(hs, EPSV);
#pragma unroll
            for (int i = 0; i < 4; ++i) hr[t][i] = hn[i] * ih;
        }
        if (it < 2) {
#pragma unroll
            for (int i = 0; i < 4; ++i)
                *(float4*)&s_ht[(d4 * 4 + i) * HSTR + g * 4] =
                    make_float4(hr[0][i], hr[1][i], hr[2][i], hr[3][i]);
            __syncwarp();   // s_ht columns are warp-private
        }
    }

    float hf[4][4];
#pragma unroll
    for (int t = 0; t < 4; ++t) {
        float hs = red16(hr[t][0] + hr[t][1] + hr[t][2] + hr[t][3]);
        float ih = 1.f / fmaxf(hs, EPSV);
#pragma unroll
        for (int i = 0; i < 4; ++i) hf[t][i] = hr[t][i] * ih;
    }
    __syncthreads();   // all warps done reading sW/sWt before region reuse

    float* s_htm = sm;
    float* s_rtm = sm + 4096;
#pragma unroll
    for (int t = 0; t < 4; ++t) {
        int tl = g * 4 + t;
        float4 hv = make_float4(hf[t][0], hf[t][1], hf[t][2], hf[t][3]);
        float4 rv = make_float4(ri[t][0], ri[t][1], ri[t][2], ri[t][3]);
        *(float4*)&s_htm[tl * 64 + d4 * 4] = hv;
        *(float4*)&s_rtm[tl * 64 + d4 * 4] = rv;
        int token = tokbase + tl;
        int bi = token >> 10, si = token & 1023;
        size_t base = ((size_t)((bi * NH + head) * NS + si)) * 64 + d4 * 4;
        *(float4*)&g_h[base] = hv;
        *(float4*)&g_hri[base] = rv;
    }
    __syncthreads();   // G1 tail reads all tokens (cross-warp)

    {
        int f4 = tid & 15, dg = tid >> 4;
        u64 acc[4][2] = {};
        float cs[4] = {};
#pragma unroll 8
        for (int o = 0; o < 64; ++o) {
            float4 hv = *(const float4*)&s_htm[o * 64 + f4 * 4];
            ulonglong2 rp = *(const ulonglong2*)&s_rtm[o * 64 + dg * 4];
            u64 h0 = dup2(hv.x), h1 = dup2(hv.y), h2 = dup2(hv.z), h3 = dup2(hv.w);
            acc[0][0] = fma2(h0, rp.x, acc[0][0]); acc[0][1] = fma2(h0, rp.y, acc[0][1]);
            acc[1][0] = fma2(h1, rp.x, acc[1][0]); acc[1][1] = fma2(h1, rp.y, acc[1][1]);
            acc[2][0] = fma2(h2, rp.x, acc[2][0]); acc[2][1] = fma2(h2, rp.y, acc[2][1]);
            acc[3][0] = fma2(h3, rp.x, acc[3][0]); acc[3][1] = fma2(h3, rp.y, acc[3][1]);
            if (dg == 0) { cs[0] += hv.x; cs[1] += hv.y; cs[2] += hv.z; cs[3] += hv.w; }
        }
        int bb = tile >> 4;
        int gsplit = tile & 15;
        int bh = bb * NH + head;
        float* gp = g_G1p + ((size_t)(bh * NSG + gsplit)) * 4096;
#pragma unroll
        for (int i = 0; i < 4; i++) {
            ulonglong2 st; st.x = acc[i][0]; st.y = acc[i][1];
            *(ulonglong2*)&gp[(f4 * 4 + i) * 64 + dg * 4] = st;
        }
        if (dg == 0) {
#pragma unroll
            for (int i = 0; i < 4; i++) g_csp[(bh * NSG + gsplit) * 64 + f4 * 4 + i] = cs[i];
        }
    }
}

// ---------------- K3b: full-chip reduction of G1 partials ----------------
__global__ void __launch_bounds__(256) g1red_kernel() {
    int bh = blockIdx.y;
    int i = blockIdx.x * 256 + threadIdx.x;
    const float* gp = g_G1p + (size_t)bh * NSG * 4096 + i;
    float s = 0.f;
#pragma unroll
    for (int p = 0; p < NSG; ++p) s += gp[p * 4096];
    g_G1[(size_t)bh * 4096 + i] = s;
}

// ---------------- K4b: iterations 0+1 in closed form (reads reduced G1) ----------------
__global__ void __launch_bounds__(256) alpha01_kernel() {
    __shared__ float sW[4096];
    __shared__ float sG[4096];
    __shared__ float s_c0[64], s_ai0[64], s_c1[64];
    int bh = blockIdx.x, tid = threadIdx.x;

    for (int i = tid; i < 4096; i += 256) sW[i] = g_Wn[i];
    for (int i = tid; i < 4096; i += 256) sG[i] = g_G1[(size_t)bh * 4096 + i];
    if (tid < 64) {
        float s = 0.f;
#pragma unroll
        for (int p = 0; p < NSG; ++p) s += g_csp[(bh * NSG + p) * 64 + tid];
        s_c0[tid] = s;
    }
    __syncthreads();
    if (tid < 64) {
        int d = tid;
        float r = 0.f;
#pragma unroll 8
        for (int f = 0; f < 64; ++f) r += s_c0[f] * sW[f * 64 + d];
        float ai = 1.f / (r + EPSV);
        s_ai0[d] = ai;
        g_aiA[bh * 64 + d] = ai;
    }
    __syncthreads();
    if (tid < 64) {
        int f = tid;
        float c1 = 0.f;
#pragma unroll 8
        for (int dd = 0; dd < 64; ++dd) {
            int d = (dd + f) & 63;
            c1 += sG[f * 64 + d] * s_ai0[d];
        }
        s_c1[f] = c1;
    }
    __syncthreads();
    if (tid < 64) {
        int d = tid;
        float r = 0.f;
#pragma unroll 8
        for (int f = 0; f < 64; ++f) r += s_c1[f] * sW[f * 64 + d];
        g_aiB[bh * 64 + d] = 1.f / (r + EPSV);
    }
}

// ---------------- K4c: pass2 — w01 per token, partial c2, partial M ----------------
__global__ void __launch_bounds__(256) pass2_kernel() {
    __shared__ __align__(16) float s_h[16][68];
    __shared__ __align__(16) float s_r[16][68];
    __shared__ float s_ai0[64], s_ai1[64];
    __shared__ float s_w[16];
    int split = blockIdx.x, bh = blockIdx.y;
    int tid = threadIdx.x;
    int f4 = tid & 15, d4 = tid >> 4;
    int lo = tid >> 4, lq = tid & 15;
    if (tid < 64) s_ai0[tid] = g_aiA[bh * 64 + tid];
    else if (tid < 128) s_ai1[tid - 64] = g_aiB[bh * 64 + tid - 64];

    const float* hb = g_h + ((size_t)bh * NS + split * OSPL) * 64;
    const float* rb = g_hri + ((size_t)bh * NS + split * OSPL) * 64;

    float accM[4][4] = {};
    float cs[4] = {};
    for (int c = 0; c < OSPL / 16; ++c) {
        *(float4*)&s_h[lo][lq * 4] = *(const float4*)&hb[(c * 16 + lo) * 64 + lq * 4];
        *(float4*)&s_r[lo][lq * 4] = *(const float4*)&rb[(c * 16 + lo) * 64 + lq * 4];
        __syncthreads();
        {
            int tt = tid >> 4;
            float4 v = *(const float4*)&s_r[tt][lq * 4];
            int base = lq * 4;
            float u0 = v.x * s_ai0[base] + v.y * s_ai0[base + 1] + v.z * s_ai0[base + 2] + v.w * s_ai0[base + 3];
            float u1 = v.x * s_ai1[base] + v.y * s_ai1[base + 1] + v.z * s_ai1[base + 2] + v.w * s_ai1[base + 3];
            u0 = red16(u0);
            u1 = red16(u1);
            if (lq == 0) s_w[tt] = u0 * u1;
        }
        __syncthreads();
#pragma unroll
        for (int o = 0; o < 16; ++o) {
            float wo = s_w[o];
            float4 hv = *(const float4*)&s_h[o][f4 * 4];
            float4 rv = *(const float4*)&s_r[o][d4 * 4];
            float hw[4] = {hv.x * wo, hv.y * wo, hv.z * wo, hv.w * wo};
            float rvv[4] = {rv.x, rv.y, rv.z, rv.w};
#pragma unroll
            for (int i = 0; i < 4; i++)
#pragma unroll
                for (int j = 0; j < 4; j++) accM[i][j] += hw[i] * rvv[j];
            if (d4 == 0) {
#pragma unroll
                for (int i = 0; i < 4; i++) cs[i] += hw[i];
            }
        }
        __syncthreads();
    }
    float* mp = g_Mp + ((size_t)(bh * NSPLIT + split)) * 4096;
#pragma unroll
    for (int i = 0; i < 4; i++)
#pragma unroll
        for (int j = 0; j < 4; j++) mp[(f4 * 4 + i) * 64 + d4 * 4 + j] = accM[i][j];
    if (d4 == 0) {
#pragma unroll
        for (int i = 0; i < 4; i++) g_c2p[(bh * NSPLIT + split) * 64 + f4 * 4 + i] = cs[i];
    }
}

// ---------------- K4c2: full-chip reduction of M partials ----------------
__global__ void __launch_bounds__(256) mred_kernel() {
    int bh = blockIdx.y;
    int i = blockIdx.x * 256 + threadIdx.x;
    const float* mp = g_Mp + (size_t)bh * NSPLIT * 4096 + i;
    float s = 0.f;
#pragma unroll
    for (int p = 0; p < NSPLIT; ++p) s += mp[p * 4096];
    g_M[(size_t)bh * 4096 + i] = s;
}

// ---------------- K4d: ai2 + cfin = M·ai2 (reads reduced M) ----------------
__global__ void __launch_bounds__(256) alpha2cfin_kernel() {
    __shared__ float sW[4096];
    __shared__ float s_c2[64];
    __shared__ float s_ai2[64];
    __shared__ float s_p[4][64];
    int bh = blockIdx.x, tid = threadIdx.x;
    for (int i = tid; i < 4096; i += 256) sW[i] = g_Wn[i];
    if (tid < 64) {
        float s = 0.f;
#pragma unroll
        for (int p = 0; p < NSPLIT; ++p) s += g_c2p[(bh * NSPLIT + p) * 64 + tid];
        s_c2[tid] = s;
    }
    __syncthreads();
    if (tid < 64) {
        int d = tid;
        float r = 0.f;
#pragma unroll 8
        for (int f = 0; f < 64; ++f) r += s_c2[f] * sW[f * 64 + d];
        s_ai2[d] = 1.f / (r + EPSV);
    }
    __syncthreads();
    {
        int f = tid & 63, g = tid >> 6;
        const float* m = g_M + (size_t)bh * 4096;
        float partial = 0.f;
#pragma unroll
        for (int dd = 0; dd < 16; ++dd) {
            int d = g * 16 + dd;
            partial += m[f * 64 + d] * s_ai2[d];
        }
        s_p[g][f] = partial;
    }
    __syncthreads();
    if (tid < 64) {
        int b = bh / NH, head = bh % NH;
        g_cfin[b * NE + head * 64 + tid] = s_p[0][tid] + s_p[1][tid] + s_p[2][tid] + s_p[3][tid];
    }
}

// ---------------- K5: out projection of the 2 unique rows ----------------
__global__ void __launch_bounds__(256) outrow_kernel(const float* __restrict__ out_w,
                                                     const float* __restrict__ out_b) {
    int b = blockIdx.y;
    int warp = threadIdx.x >> 5, lane = threadIdx.x & 31;
    int j = blockIdx.x * 8 + warp;
    const float* c = g_cfin + b * NE;
    const float* wrow = out_w + (size_t)j * NE;
    float acc = 0.f;
    for (int e = lane; e < NE; e += 32) acc += c[e] * wrow[e];
    acc = red32(acc);
    if (lane == 0) g_yrow[b * FIN + j] = acc + out_b[j];
}

// ---------------- K6: broadcast rows to all positions ----------------
__global__ void __launch_bounds__(256) bcast_kernel(float* __restrict__ out) {
    int idx = blockIdx.x * 256 + threadIdx.x;
    const int per_row = FIN / 4;
    int j4 = idx % per_row;
    int bs = idx / per_row;
    int b = bs >> 10;
    float4 v = ((const float4*)(g_yrow + b * FIN))[j4];
    ((float4*)out)[idx] = v;
}

// ---------------- launch ----------------
extern "C" void kernel_launch(void* const* d_in, const int* in_sizes, int n_in,
                              void* d_out, int out_size) {
    const float* x       = (const float*)d_in[0];
    const float* embed_w = (const float*)d_in[1];
    const float* embed_b = (const float*)d_in[2];
    const float* nnmf_w  = (const float*)d_in[3];
    const float* out_w   = (const float*)d_in[4];
    const float* out_b   = (const float*)d_in[5];
    float* out = (float*)d_out;

    static bool attr_set = false;
    if (!attr_set) {
        cudaFuncSetAttribute(nnmf_kernel, cudaFuncAttributeMaxDynamicSharedMemorySize,
                             NN_SMEM_BYTES);
        attr_set = true;
    }

    wnorm_kernel<<<1, 64>>>(nnmf_w);
    conv_kernel<<<2112, 256>>>(x, embed_w);
    embed_mma_kernel<<<dim3(NE / 64, (NB * NS) / 128), 256>>>(embed_b);
    nnmf_kernel<<<dim3((NB * NS) / 64, NH), 256, NN_SMEM_BYTES>>>();
    g1red_kernel<<<dim3(16, NBH), 256>>>();
    alpha01_kernel<<<NBH, 256>>>();
    pass2_kernel<<<dim3(NSPLIT, NBH), 256>>>();
    mred_kernel<<<dim3(16, NBH), 256>>>();
    alpha2cfin_kernel<<<NBH, 256>>>();
    outrow_kernel<<<dim3(NE / 8, NB), 256>>>(out_w, out_b);
    bcast_kernel<<<(NB * NS * (FIN / 4)) / 256, 256>>>(out);
}

// round 16
// speedup vs baseline: 1.0078x; 1.0078x over previous
#include <cuda_runtime.h>
#include <cuda_bf16.h>
#include <cstdint>

#define NB 2
#define NS 1024
#define FIN 768
#define NE 768
#define NH 12
#define NBH (NB * NH)
#define NDH 64
#define NFH 64
#define NSPLIT 16
#define OSPL (NS / NSPLIT)   // 64 tokens per split (pass2)
#define NSG 16               // g1 splits (64 tokens each, fused in nnmf)
#define MIN_POS 1e-6f
#define EPSV 1e-20f
#define K3 2304              // tripled K for bf16-split GEMM
#define HSTR 68              // feature-major row stride (floats): 64 tokens + 4 pad
#define NN_SMEM_BYTES ((4096 + 4096 + 64 * HSTR * 2) * 4)

typedef unsigned long long u64;

// ---------------- scratch (device globals; no allocation) ----------------
__device__ __align__(16) float g_Wn[NFH * NDH];                 // normalized W [f][d]
__device__ __align__(16) float g_Wt[NDH * NFH];                 // transposed normalized W [d][f]
__device__ __align__(16) float g_rec0[NDH];                     // (1/64)*colsum(W) — iteration-0 rec
__device__ __align__(16) __nv_bfloat16 g_Abf[2048 * K3];        // [hi | hi | lo] of X
__device__ __align__(16) __nv_bfloat16 g_Wbf[768 * K3];         // [hi | lo | hi] of embed_w
__device__ __align__(16) float g_xe[NB * NS * NE];              // clipped embed output
__device__ __align__(16) float g_h[NBH * NS * NFH];             // h   [bh][s][f]
__device__ __align__(16) float g_hri[NBH * NS * NDH];           // rec*inp [bh][s][d]
__device__ __align__(16) float g_G1p[NBH * NSG * 64 * 64];      // partial h^T*hri
__device__ __align__(16) float g_G1[NBH * 64 * 64];             // reduced h^T*hri
__device__ __align__(16) float g_Mp[NBH * NSPLIT * 64 * 64];    // partial h^T*(w01*hri)
__device__ __align__(16) float g_M[NBH * 64 * 64];              // reduced M
__device__ __align__(16) float g_csp[NBH * NSG * 64];           // partial colsum(h)
__device__ __align__(16) float g_c2p[NBH * NSPLIT * 64];        // partial c2
__device__ __align__(16) float g_aiA[NBH * 64];                 // arec_inv iter0
__device__ __align__(16) float g_aiB[NBH * 64];                 // arec_inv iter1
__device__ __align__(16) float g_cfin[NB * NE];                 // final mixed row per batch
__device__ __align__(16) float g_yrow[NB * FIN];                // final projected row per batch

// ---------------- helpers ----------------
__device__ __forceinline__ float red16(float v) {
    v += __shfl_xor_sync(0xffffffffu, v, 8);
    v += __shfl_xor_sync(0xffffffffu, v, 4);
    v += __shfl_xor_sync(0xffffffffu, v, 2);
    v += __shfl_xor_sync(0xffffffffu, v, 1);
    return v;
}
__device__ __forceinline__ float red32(float v) {
    v += __shfl_xor_sync(0xffffffffu, v, 16);
    return red16(v);
}
__device__ __forceinline__ uint32_t pack2(__nv_bfloat16 a, __nv_bfloat16 b) {
    __nv_bfloat162 t = __halves2bfloat162(a, b);
    return *reinterpret_cast<uint32_t*>(&t);
}
__device__ __forceinline__ void ldsm4(uint32_t* r, uint32_t addr) {
    asm volatile("ldmatrix.sync.aligned.m8n8.x4.shared.b16 {%0,%1,%2,%3}, [%4];"
                 : "=r"(r[0]), "=r"(r[1]), "=r"(r[2]), "=r"(r[3]) : "r"(addr));
}
__device__ __forceinline__ void mma_bf16(float* c, const uint32_t* a, uint32_t b0, uint32_t b1) {
    asm volatile(
        "mma.sync.aligned.m16n8k16.row.col.f32.bf16.bf16.f32 "
        "{%0,%1,%2,%3}, {%4,%5,%6,%7}, {%8,%9}, {%0,%1,%2,%3};\n"
        : "+f"(c[0]), "+f"(c[1]), "+f"(c[2]), "+f"(c[3])
        : "r"(a[0]), "r"(a[1]), "r"(a[2]), "r"(a[3]), "r"(b0), "r"(b1));
}
// packed fp32x2 helpers (FFMA2 is PTX-only; ptxas never auto-fuses)
__device__ __forceinline__ u64 fma2(u64 a, u64 b, u64 c) {
    u64 d;
    asm("fma.rn.f32x2 %0, %1, %2, %3;" : "=l"(d) : "l"(a), "l"(b), "l"(c));
    return d;
}
__device__ __forceinline__ u64 dup2(float x) {
    u64 d;
    uint32_t r = __float_as_uint(x);
    asm("mov.b64 %0, {%1, %2};" : "=l"(d) : "r"(r), "r"(r));
    return d;
}
__device__ __forceinline__ float2 unpk2(u64 v) {
    uint32_t lo, hi;
    asm("mov.b64 {%0, %1}, %2;" : "=r"(lo), "=r"(hi) : "l"(v));
    return make_float2(__uint_as_float(lo), __uint_as_float(hi));
}

// ---------------- K1: normalize nnmf_w rows (+ transpose + rec0) ----------------
__global__ void wnorm_kernel(const float* __restrict__ nnmf_w) {
    int f = threadIdx.x;  // 0..63
    float s = 0.f;
#pragma unroll
    for (int d = 0; d < NDH; ++d) s += nnmf_w[f * NDH + d];
    s = fmaxf(s, EPSV);
    float inv = 1.f / s;
#pragma unroll
    for (int d = 0; d < NDH; ++d) {
        float v = nnmf_w[f * NDH + d] * inv;
        g_Wn[f * NDH + d] = v;
        g_Wt[d * NFH + f] = v;
    }
    __syncthreads();
    {
        int d = f;
        float c = 0.f;
#pragma unroll
        for (int ff = 0; ff < NFH; ++ff) c += g_Wn[ff * NDH + d];
        g_rec0[d] = c * (1.f / 64.f);
    }
}

// ---------------- K2a: bf16 split conversion of X and embed_w ----------------
__global__ void __launch_bounds__(256) conv_kernel(const float* __restrict__ X,
                                                   const float* __restrict__ Wm) {
    int i = blockIdx.x * 256 + threadIdx.x;
    int row = i / 192, q = (i % 192) * 4;
    const float* src = (row < 2048) ? X + (size_t)row * 768 + q
                                    : Wm + (size_t)(row - 2048) * 768 + q;
    float4 v = *(const float4*)src;
    float xs[4] = {v.x, v.y, v.z, v.w};
    __nv_bfloat16 hi[4], lo[4];
#pragma unroll
    for (int j = 0; j < 4; ++j) {
        hi[j] = __float2bfloat16(xs[j]);
        lo[j] = __float2bfloat16(xs[j] - __bfloat162float(hi[j]));
    }
    uint2 hv = make_uint2(pack2(hi[0], hi[1]), pack2(hi[2], hi[3]));
    uint2 lv = make_uint2(pack2(lo[0], lo[1]), pack2(lo[2], lo[3]));
    if (row < 2048) {
        __nv_bfloat16* dst = g_Abf + (size_t)row * K3 + q;
        *(uint2*)(dst)        = hv;
        *(uint2*)(dst + 768)  = hv;
        *(uint2*)(dst + 1536) = lv;
    } else {
        __nv_bfloat16* dst = g_Wbf + (size_t)(row - 2048) * K3 + q;
        *(uint2*)(dst)        = hv;
        *(uint2*)(dst + 768)  = lv;
        *(uint2*)(dst + 1536) = hv;
    }
}

// ---------------- K2b: embed GEMM, bf16 mma, double-buffered ----------------
__global__ void __launch_bounds__(256) embed_mma_kernel(const float* __restrict__ bias) {
    __shared__ __align__(16) __nv_bfloat16 As[2][128 * 40];
    __shared__ __align__(16) __nv_bfloat16 Bs[2][64 * 40];
    int tid = threadIdx.x;
    int bm = blockIdx.y * 128, bn = blockIdx.x * 64;
    int wid = tid >> 5, lane = tid & 31;
    int wm = wid & 3, wn = wid >> 2;

    float c[2][4][4];
#pragma unroll
    for (int mt = 0; mt < 2; ++mt)
#pragma unroll
        for (int nt = 0; nt < 4; ++nt)
#pragma unroll
            for (int r = 0; r < 4; ++r) c[mt][nt][r] = 0.f;

    const uint32_t ABUF = 128 * 40 * 2;
    const uint32_t BBUF = 64 * 40 * 2;
    uint32_t a_base[2], b_base[2];
#pragma unroll
    for (int mt = 0; mt < 2; ++mt) {
        int row = wm * 32 + mt * 16 + (lane & 15);
        int colhalf = lane >> 4;
        a_base[mt] = (uint32_t)__cvta_generic_to_shared(&As[0][row * 40 + colhalf * 8]);
    }
#pragma unroll
    for (int bt = 0; bt < 2; ++bt) {
        int n = wn * 32 + bt * 16 + ((lane >> 4) << 3) + (lane & 7);
        int khalf = (lane >> 3) & 1;
        b_base[bt] = (uint32_t)__cvta_generic_to_shared(&Bs[0][n * 40 + khalf * 8]);
    }

    int am0 = tid >> 2, ac0 = (tid & 3) * 8;
    int am1 = (tid + 256) >> 2, ac1 = ((tid + 256) & 3) * 8;
    int bn0 = tid >> 2, bc0 = (tid & 3) * 8;
    const __nv_bfloat16* arow0 = g_Abf + (size_t)(bm + am0) * K3 + ac0;
    const __nv_bfloat16* arow1 = g_Abf + (size_t)(bm + am1) * K3 + ac1;
    const __nv_bfloat16* brow0 = g_Wbf + (size_t)(bn + bn0) * K3 + bc0;

    {
        *(uint4*)&As[0][am0 * 40 + ac0] = *(const uint4*)(arow0);
        *(uint4*)&As[0][am1 * 40 + ac1] = *(const uint4*)(arow1);
        *(uint4*)&Bs[0][bn0 * 40 + bc0] = *(const uint4*)(brow0);
    }
    __syncthreads();

    for (int ks = 0; ks < 72; ++ks) {
        int cur = ks & 1, nxt = cur ^ 1;
        uint4 na0, na1, nb;
        if (ks < 71) {
            int k0n = (ks + 1) * 32;
            na0 = *(const uint4*)(arow0 + k0n);
            na1 = *(const uint4*)(arow1 + k0n);
            nb  = *(const uint4*)(brow0 + k0n);
        }
        uint32_t aoff = cur * ABUF, boff = cur * BBUF;
#pragma unroll
        for (int kh = 0; kh < 2; ++kh) {
            int kk = kh * 16;
            uint32_t a[2][4], b[2][4];
            ldsm4(a[0], a_base[0] + aoff + kk * 2);
            ldsm4(a[1], a_base[1] + aoff + kk * 2);
            ldsm4(b[0], b_base[0] + boff + kk * 2);
            ldsm4(b[1], b_base[1] + boff + kk * 2);
#pragma unroll
            for (int mt = 0; mt < 2; ++mt)
#pragma unroll
                for (int nt = 0; nt < 4; ++nt)
                    mma_bf16(c[mt][nt], a[mt], b[nt >> 1][(nt & 1) * 2], b[nt >> 1][(nt & 1) * 2 + 1]);
        }
        if (ks < 71) {
            *(uint4*)&As[nxt][am0 * 40 + ac0] = na0;
            *(uint4*)&As[nxt][am1 * 40 + ac1] = na1;
            *(uint4*)&Bs[nxt][bn0 * 40 + bc0] = nb;
        }
        __syncthreads();
    }

#pragma unroll
    for (int mt = 0; mt < 2; ++mt) {
#pragma unroll
        for (int nt = 0; nt < 4; ++nt) {
            int m0 = bm + wm * 32 + mt * 16 + (lane >> 2);
            int n0 = bn + wn * 32 + nt * 8 + (lane & 3) * 2;
            float2 bv = *(const float2*)&bias[n0];
            float2 o0, o1;
            o0.x = fmaxf(c[mt][nt][0] + bv.x, MIN_POS);
            o0.y = fmaxf(c[mt][nt][1] + bv.y, MIN_POS);
            o1.x = fmaxf(c[mt][nt][2] + bv.x, MIN_POS);
            o1.y = fmaxf(c[mt][nt][3] + bv.y, MIN_POS);
            *(float2*)&g_xe[(size_t)m0 * NE + n0] = o0;
            *(float2*)&g_xe[(size_t)(m0 + 8) * NE + n0] = o1;
        }
    }
}

// ---------------- K3: fused NNMF — warp-private token columns, __syncwarp inner sync ----------------
// thread (g = tid>>4, d4 = tid&15); warp w owns token columns 8w..8w+7 of s_ht/s_rt
// (disjoint across warps), and red16 shuffles stay inside 16-lane groups, so the
// iteration loop needs only warp-level sync. Block barriers remain only around the
// cooperative W load and the cross-warp G1 tail.
__global__ void __launch_bounds__(256, 3) nnmf_kernel() {
    extern __shared__ float sm[];
    float* sW   = sm;
    float* sWt  = sm + 4096;
    float* s_ht = sm + 8192;
    float* s_rt = sm + 8192 + 64 * HSTR;

    int head = blockIdx.y;
    int tile = blockIdx.x;
    int tid = threadIdx.x;
    int d4 = tid & 15;
    int g = tid >> 4;
    int tokbase = tile * 64;

    for (int i = tid; i < 4096; i += 256) sW[i] = g_Wn[i];
    for (int i = tid; i < 4096; i += 256) sWt[i] = g_Wt[i];

    float inp[4][4];
#pragma unroll
    for (int t = 0; t < 4; ++t) {
        int tok = tokbase + g * 4 + t;
        float4 x = *(const float4*)&g_xe[(size_t)tok * NE + head * 64 + d4 * 4];
        float s = red16(x.x + x.y + x.z + x.w);
        float iv = 1.f / fmaxf(s, EPSV);
        inp[t][0] = x.x * iv; inp[t][1] = x.y * iv; inp[t][2] = x.z * iv; inp[t][3] = x.w * iv;
    }

    {
        float4 r0 = *(const float4*)&g_rec0[d4 * 4];
        float rd[4] = {1.f / fmaxf(r0.x, MIN_POS), 1.f / fmaxf(r0.y, MIN_POS),
                       1.f / fmaxf(r0.z, MIN_POS), 1.f / fmaxf(r0.w, MIN_POS)};
#pragma unroll
        for (int i = 0; i < 4; ++i)
            *(float4*)&s_rt[(d4 * 4 + i) * HSTR + g * 4] =
                make_float4(inp[0][i] * rd[i], inp[1][i] * rd[i],
                            inp[2][i] * rd[i], inp[3][i] * rd[i]);
    }
    __syncthreads();   // W smem load complete (also covers initial s_rt)

    const float hinit = 1.f / 64.f;
    float hr[4][4];
    float ri[4][4];

    for (int it = 0; it < 3; ++it) {
        if (it > 0) {
            u64 a[4][2] = {};
#pragma unroll 8
            for (int ff = 0; ff < 64; ++ff) {
                ulonglong2 hp = *(const ulonglong2*)&s_ht[ff * HSTR + g * 4];
                float4 w = *(const float4*)&sW[ff * 64 + d4 * 4];
                u64 w0 = dup2(w.x), w1 = dup2(w.y), w2 = dup2(w.z), w3 = dup2(w.w);
                a[0][0] = fma2(w0, hp.x, a[0][0]); a[0][1] = fma2(w0, hp.y, a[0][1]);
                a[1][0] = fma2(w1, hp.x, a[1][0]); a[1][1] = fma2(w1, hp.y, a[1][1]);
                a[2][0] = fma2(w2, hp.x, a[2][0]); a[2][1] = fma2(w2, hp.y, a[2][1]);
                a[3][0] = fma2(w3, hp.x, a[3][0]); a[3][1] = fma2(w3, hp.y, a[3][1]);
            }
            float av[4][4];
#pragma unroll
            for (int i = 0; i < 4; ++i) {
                float2 u0 = unpk2(a[i][0]), u1 = unpk2(a[i][1]);
                av[0][i] = fmaxf(u0.x, MIN_POS); av[1][i] = fmaxf(u0.y, MIN_POS);
                av[2][i] = fmaxf(u1.x, MIN_POS); av[3][i] = fmaxf(u1.y, MIN_POS);
            }
            if (it == 2) {
#pragma unroll
                for (int t = 0; t < 4; ++t)
#pragma unroll
                    for (int i = 0; i < 4; ++i) ri[t][i] = av[t][i] * inp[t][i];
            }
#pragma unroll
            for (int i = 0; i < 4; ++i) {
                float q0 = __fdividef(inp[0][i], av[0][i]);
                float q1 = __fdividef(inp[1][i], av[1][i]);
                float q2 = __fdividef(inp[2][i], av[2][i]);
                float q3 = __fdividef(inp[3][i], av[3][i]);
                *(float4*)&s_rt[(d4 * 4 + i) * HSTR + g * 4] = make_float4(q0, q1, q2, q3);
            }
            __syncwarp();   // s_rt columns are warp-private
        }

        u64 b[4][2] = {};
#pragma unroll 8
        for (int d = 0; d < 64; ++d) {
            ulonglong2 rp = *(const ulonglong2*)&s_rt[d * HSTR + g * 4];
            float4 wt = *(const float4*)&sWt[d * 64 + d4 * 4];
            u64 w0 = dup2(wt.x), w1 = dup2(wt.y), w2 = dup2(wt.z), w3 = dup2(wt.w);
            b[0][0] = fma2(w0, rp.x, b[0][0]); b[0][1] = fma2(w0, rp.y, b[0][1]);
            b[1][0] = fma2(w1, rp.x, b[1][0]); b[1][1] = fma2(w1, rp.y, b[1][1]);
            b[2][0] = fma2(w2, rp.x, b[2][0]); b[2][1] = fma2(w2, rp.y, b[2][1]);
            b[3][0] = fma2(w3, rp.x, b[3][0]); b[3][1] = fma2(w3, rp.y, b[3][1]);
        }
        float bv[4][4];
#pragma unroll
        for (int i = 0; i < 4; ++i) {
            float2 u0 = unpk2(b[i][0]), u1 = unpk2(b[i][1]);
            bv[0][i] = u0.x; bv[1][i] = u0.y; bv[2][i] = u1.x; bv[3][i] = u1.y;
        }
#pragma unroll
        for (int t = 0; t < 4; ++t) {
            float hn[4];
#pragma unroll
            for (int i = 0; i < 4; ++i) {
                float pre = (it == 0) ? hinit : hr[t][i];
                hn[i] = fmaxf(pre * bv[t][i], MIN_POS);
            }
            float hs = red16(hn[0] + hn[1] + hn[2] + hn[3]);
            float ih = 1.f / fmaxf(hs, EPSV);
#pragma unroll
            for (int i = 0; i < 4; ++i) hr[t][i] = hn[i] * ih;
        }
        if (it < 2) {
#pragma unroll
            for (int i = 0; i < 4; ++i)
                *(float4*)&s_ht[(d4 * 4 + i) * HSTR + g * 4] =
                    make_float4(hr[0][i], hr[1][i], hr[2][i], hr[3][i]);
            __syncwarp();   // s_ht columns are warp-private
        }
    }

    float hf[4][4];
#pragma unroll
    for (int t = 0; t < 4; ++t) {
        float hs = red16(hr[t][0] + hr[t][1] + hr[t][2] + hr[t][3]);
        float ih = 1.f / fmaxf(hs, EPSV);
#pragma unroll
        for (int i = 0; i < 4; ++i) hf[t][i] = hr[t][i] * ih;
    }
    __syncthreads();   // all warps done reading sW/sWt before region reuse

    float* s_htm = sm;
    float* s_rtm = sm + 4096;
#pragma unroll
    for (int t = 0; t < 4; ++t) {
        int tl = g * 4 + t;
        float4 hv = make_float4(hf[t][0], hf[t][1], hf[t][2], hf[t][3]);
        float4 rv = make_float4(ri[t][0], ri[t][1], ri[t][2], ri[t][3]);
        *(float4*)&s_htm[tl * 64 + d4 * 4] = hv;
        *(float4*)&s_rtm[tl * 64 + d4 * 4] = rv;
        int token = tokbase + tl;
        int bi = token >> 10, si = token & 1023;
        size_t base = ((size_t)((bi * NH + head) * NS + si)) * 64 + d4 * 4;
        *(float4*)&g_h[base] = hv;
        *(float4*)&g_hri[base] = rv;
    }
    __syncthreads();   // G1 tail reads all tokens (cross-warp)

    {
        int f4 = tid & 15, dg = tid >> 4;
        u64 acc[4][2] = {};
        float cs[4] = {};
#pragma unroll 8
        for (int o = 0; o < 64; ++o) {
            float4 hv = *(const float4*)&s_htm[o * 64 + f4 * 4];
            ulonglong2 rp = *(const ulonglong2*)&s_rtm[o * 64 + dg * 4];
            u64 h0 = dup2(hv.x), h1 = dup2(hv.y), h2 = dup2(hv.z), h3 = dup2(hv.w);
            acc[0][0] = fma2(h0, rp.x, acc[0][0]); acc[0][1] = fma2(h0, rp.y, acc[0][1]);
            acc[1][0] = fma2(h1, rp.x, acc[1][0]); acc[1][1] = fma2(h1, rp.y, acc[1][1]);
            acc[2][0] = fma2(h2, rp.x, acc[2][0]); acc[2][1] = fma2(h2, rp.y, acc[2][1]);
            acc[3][0] = fma2(h3, rp.x, acc[3][0]); acc[3][1] = fma2(h3, rp.y, acc[3][1]);
            if (dg == 0) { cs[0] += hv.x; cs[1] += hv.y; cs[2] += hv.z; cs[3] += hv.w; }
        }
        int bb = tile >> 4;
        int gsplit = tile & 15;
        int bh = bb * NH + head;
        float* gp = g_G1p + ((size_t)(bh * NSG + gsplit)) * 4096;
#pragma unroll
        for (int i = 0; i < 4; i++) {
            ulonglong2 st; st.x = acc[i][0]; st.y = acc[i][1];
            *(ulonglong2*)&gp[(f4 * 4 + i) * 64 + dg * 4] = st;
        }
        if (dg == 0) {
#pragma unroll
            for (int i = 0; i < 4; i++) g_csp[(bh * NSG + gsplit) * 64 + f4 * 4 + i] = cs[i];
        }
    }
}

// ---------------- K3b: full-chip reduction of G1 partials ----------------
__global__ void __launch_bounds__(256) g1red_kernel() {
    int bh = blockIdx.y;
    int i = blockIdx.x * 256 + threadIdx.x;
    const float* gp = g_G1p + (size_t)bh * NSG * 4096 + i;
    float s = 0.f;
#pragma unroll
    for (int p = 0; p < NSG; ++p) s += gp[p * 4096];
    g_G1[(size_t)bh * 4096 + i] = s;
}

// ---------------- K4b: iterations 0+1 in closed form (reads reduced G1) ----------------
__global__ void __launch_bounds__(256) alpha01_kernel() {
    __shared__ float sW[4096];
    __shared__ float sG[4096];
    __shared__ float s_c0[64], s_ai0[64], s_c1[64];
    int bh = blockIdx.x, tid = threadIdx.x;

    for (int i = tid; i < 4096; i += 256) sW[i] = g_Wn[i];
    for (int i = tid; i < 4096; i += 256) sG[i] = g_G1[(size_t)bh * 4096 + i];
    if (tid < 64) {
        float s = 0.f;
#pragma unroll
        for (int p = 0; p < NSG; ++p) s += g_csp[(bh * NSG + p) * 64 + tid];
        s_c0[tid] = s;
    }
    __syncthreads();
    if (tid < 64) {
        int d = tid;
        float r = 0.f;
#pragma unroll 8
        for (int f = 0; f < 64; ++f) r += s_c0[f] * sW[f * 64 + d];
        float ai = 1.f / (r + EPSV);
        s_ai0[d] = ai;
        g_aiA[bh * 64 + d] = ai;
    }
    __syncthreads();
    if (tid < 64) {
        int f = tid;
        float c1 = 0.f;
#pragma unroll 8
        for (int dd = 0; dd < 64; ++dd) {
            int d = (dd + f) & 63;
            c1 += sG[f * 64 + d] * s_ai0[d];
        }
        s_c1[f] = c1;
    }
    __syncthreads();
    if (tid < 64) {
        int d = tid;
        float r = 0.f;
#pragma unroll 8
        for (int f = 0; f < 64; ++f) r += s_c1[f] * sW[f * 64 + d];
        g_aiB[bh * 64 + d] = 1.f / (r + EPSV);
    }
}

// ---------------- K4c: pass2 — w01 per token, partial c2, partial M ----------------
__global__ void __launch_bounds__(256) pass2_kernel() {
    __shared__ __align__(16) float s_h[16][68];
    __shared__ __align__(16) float s_r[16][68];
    __shared__ float s_ai0[64], s_ai1[64];
    __shared__ float s_w[16];
    int split = blockIdx.x, bh = blockIdx.y;
    int tid = threadIdx.x;
    int f4 = tid & 15, d4 = tid >> 4;
    int lo = tid >> 4, lq = tid & 15;
    if (tid < 64) s_ai0[tid] = g_aiA[bh * 64 + tid];
    else if (tid < 128) s_ai1[tid - 64] = g_aiB[bh * 64 + tid - 64];

    const float* hb = g_h + ((size_t)bh * NS + split * OSPL) * 64;
    const float* rb = g_hri + ((size_t)bh * NS + split * OSPL) * 64;

    float accM[4][4] = {};
    float cs[4] = {};
    for (int c = 0; c < OSPL / 16; ++c) {
        *(float4*)&s_h[lo][lq * 4] = *(const float4*)&hb[(c * 16 + lo) * 64 + lq * 4];
        *(float4*)&s_r[lo][lq * 4] = *(const float4*)&rb[(c * 16 + lo) * 64 + lq * 4];
        __syncthreads();
        {
            int tt = tid >> 4;
            float4 v = *(const float4*)&s_r[tt][lq * 4];
            int base = lq * 4;
            float u0 = v.x * s_ai0[base] + v.y * s_ai0[base + 1] + v.z * s_ai0[base + 2] + v.w * s_ai0[base + 3];
            float u1 = v.x * s_ai1[base] + v.y * s_ai1[base + 1] + v.z * s_ai1[base + 2] + v.w * s_ai1[base + 3];
            u0 = red16(u0);
            u1 = red16(u1);
            if (lq == 0) s_w[tt] = u0 * u1;
        }
        __syncthreads();
#pragma unroll
        for (int o = 0; o < 16; ++o) {
            float wo = s_w[o];
            float4 hv = *(const float4*)&s_h[o][f4 * 4];
            float4 rv = *(const float4*)&s_r[o][d4 * 4];
            float hw[4] = {hv.x * wo, hv.y * wo, hv.z * wo, hv.w * wo};
            float rvv[4] = {rv.x, rv.y, rv.z, rv.w};
#pragma unroll
            for (int i = 0; i < 4; i++)
#pragma unroll
                for (int j = 0; j < 4; j++) accM[i][j] += hw[i] * rvv[j];
            if (d4 == 0) {
#pragma unroll
                for (int i = 0; i < 4; i++) cs[i] += hw[i];
            }
        }
        __syncthreads();
    }
    float* mp = g_Mp + ((size_t)(bh * NSPLIT + split)) * 4096;
#pragma unroll
    for (int i = 0; i < 4; i++)
#pragma unroll
        for (int j = 0; j < 4; j++) mp[(f4 * 4 + i) * 64 + d4 * 4 + j] = accM[i][j];
    if (d4 == 0) {
#pragma unroll
        for (int i = 0; i < 4; i++) g_c2p[(bh * NSPLIT + split) * 64 + f4 * 4 + i] = cs[i];
    }
}

// ---------------- K4c2: full-chip reduction of M partials ----------------
__global__ void __launch_bounds__(256) mred_kernel() {
    int bh = blockIdx.y;
    int i = blockIdx.x * 256 + threadIdx.x;
    const float* mp = g_Mp + (size_t)bh * NSPLIT * 4096 + i;
    float s = 0.f;
#pragma unroll
    for (int p = 0; p < NSPLIT; ++p) s += mp[p * 4096];
    g_M[(size_t)bh * 4096 + i] = s;
}

// ---------------- K4d: ai2 + cfin = M·ai2 (reads reduced M) ----------------
__global__ void __launch_bounds__(256) alpha2cfin_kernel() {
    __shared__ float sW[4096];
    __shared__ float s_c2[64];
    __shared__ float s_ai2[64];
    __shared__ float s_p[4][64];
    int bh = blockIdx.x, tid = threadIdx.x;
    for (int i = tid; i < 4096; i += 256) sW[i] = g_Wn[i];
    if (tid < 64) {
        float s = 0.f;
#pragma unroll
        for (int p = 0; p < NSPLIT; ++p) s += g_c2p[(bh * NSPLIT + p) * 64 + tid];
        s_c2[tid] = s;
    }
    __syncthreads();
    if (tid < 64) {
        int d = tid;
        float r = 0.f;
#pragma unroll 8
        for (int f = 0; f < 64; ++f) r += s_c2[f] * sW[f * 64 + d];
        s_ai2[d] = 1.f / (r + EPSV);
    }
    __syncthreads();
    {
        int f = tid & 63, g = tid >> 6;
        const float* m = g_M + (size_t)bh * 4096;
        float partial = 0.f;
#pragma unroll
        for (int dd = 0; dd < 16; ++dd) {
            int d = g * 16 + dd;
            partial += m[f * 64 + d] * s_ai2[d];
        }
        s_p[g][f] = partial;
    }
    __syncthreads();
    if (tid < 64) {
        int b = bh / NH, head = bh % NH;
        g_cfin[b * NE + head * 64 + tid] = s_p[0][tid] + s_p[1][tid] + s_p[2][tid] + s_p[3][tid];
    }
}

// ---------------- K5: out projection of the 2 unique rows ----------------
__global__ void __launch_bounds__(256) outrow_kernel(const float* __restrict__ out_w,
                                                     const float* __restrict__ out_b) {
    int b = blockIdx.y;
    int warp = threadIdx.x >> 5, lane = threadIdx.x & 31;
    int j = blockIdx.x * 8 + warp;
    const float* c = g_cfin + b * NE;
    const float* wrow = out_w + (size_t)j * NE;
    float acc = 0.f;
    for (int e = lane; e < NE; e += 32) acc += c[e] * wrow[e];
    acc = red32(acc);
    if (lane == 0) g_yrow[b * FIN + j] = acc + out_b[j];
}

// ---------------- K6: broadcast rows to all positions ----------------
__global__ void __launch_bounds__(256) bcast_kernel(float* __restrict__ out) {
    int idx = blockIdx.x * 256 + threadIdx.x;
    const int per_row = FIN / 4;
    int j4 = idx % per_row;
    int bs = idx / per_row;
    int b = bs >> 10;
    float4 v = ((const float4*)(g_yrow + b * FIN))[j4];
    ((float4*)out)[idx] = v;
}

// ---------------- launch ----------------
extern "C" void kernel_launch(void* const* d_in, const int* in_sizes, int n_in,
                              void* d_out, int out_size) {
    const float* x       = (const float*)d_in[0];
    const float* embed_w = (const float*)d_in[1];
    const float* embed_b = (const float*)d_in[2];
    const float* nnmf_w  = (const float*)d_in[3];
    const float* out_w   = (const float*)d_in[4];
    const float* out_b   = (const float*)d_in[5];
    float* out = (float*)d_out;

    static bool attr_set = false;
    if (!attr_set) {
        cudaFuncSetAttribute(nnmf_kernel, cudaFuncAttributeMaxDynamicSharedMemorySize,
                             NN_SMEM_BYTES);
        attr_set = true;
    }

    wnorm_kernel<<<1, 64>>>(nnmf_w);
    conv_kernel<<<2112, 256>>>(x, embed_w);
    embed_mma_kernel<<<dim3(NE / 64, (NB * NS) / 128), 256>>>(embed_b);
    nnmf_kernel<<<dim3((NB * NS) / 64, NH), 256, NN_SMEM_BYTES>>>();
    g1red_kernel<<<dim3(16, NBH), 256>>>();
    alpha01_kernel<<<NBH, 256>>>();
    pass2_kernel<<<dim3(NSPLIT, NBH), 256>>>();
    mred_kernel<<<dim3(16, NBH), 256>>>();
    alpha2cfin_kernel<<<NBH, 256>>>();
    outrow_kernel<<<dim3(NE / 8, NB), 256>>>(out_w, out_b);
    bcast_kernel<<<(NB * NS * (FIN / 4)) / 256, 256>>>(out);
}